// round 3
// baseline (speedup 1.0000x reference)
#include <cuda_runtime.h>
#include <cstring>

typedef unsigned long long u64;

#define N_MAX   400000
#define CIN     32
#define COUT    64
#define OZ      100
#define OY      100
#define OX      8
#define NUM_OUT (2*OZ*OY*OX)           /* 160000 */
#define MAXP    (8*N_MAX)              /* 3.2M max pairs */
#define PPB     2048                   /* pairs per gemm block */
#define MAXCHUNK ((N_MAX + PPB - 1)/PPB)
#define VS_BLOCKS (NUM_OUT/256)        /* 625 scan blocks */

/* ------------------ device scratch (static, no allocs) ------------------ */
__device__ int      g_hist[65536];
__device__ int      g_sel[2];
__device__ unsigned g_thr;
__device__ int      g_offcnt[27];
__device__ int      g_offstart[28];
__device__ int      g_cursor[27];
__device__ int      g_keep[NUM_OUT];
__device__ int      g_voxcnt[NUM_OUT];
__device__ int      g_vstart[NUM_OUT + 1];
__device__ int      g_vcursor[NUM_OUT];
__device__ int      g_vbsum[VS_BLOCKS];
__device__ int      g_vboff[VS_BLOCKS];
__device__ int      g_pair_idx[MAXP];
__device__ int      g_pair_dst[MAXP];
__device__ float    g_scratch[(size_t)MAXP * 64];   /* per-pair 64-ch partial rows */

/* ------------------ helpers ------------------ */
__device__ __forceinline__ unsigned fkey(float x) {
    unsigned u = __float_as_uint(x);
    return (u & 0x80000000u) ? ~u : (u | 0x80000000u);
}
__device__ __forceinline__ u64 ffma2(u64 a, u64 b, u64 c) {
    u64 d;
    asm("fma.rn.f32x2 %0, %1, %2, %3;" : "=l"(d) : "l"(a), "l"(b), "l"(c));
    return d;
}
__device__ __forceinline__ u64 fadd2(u64 a, u64 b) {
    u64 d;
    asm("add.rn.f32x2 %0, %1, %2;" : "=l"(d) : "l"(a), "l"(b));
    return d;
}
__device__ __forceinline__ u64 dup2(float v) {
    float2 t = make_float2(v, v);
    u64 r; memcpy(&r, &t, 8); return r;
}

/* enumerate valid (offset, output voxel) pairs for one point: <= 8 */
__device__ __forceinline__ int enum_off(int b, int z, int y, int x, int* ol, int* vl) {
    int zo[2], zc[2]; int nzc = 0;
    int yo[2], yc[2]; int nyc = 0;
    int xo[2], xc[2]; int nxc = 0;
#pragma unroll
    for (int o = 0; o < 3; o++) {
        int nz = z + 1 - o;
        if (nz >= 0 && !(nz & 1)) { int c = nz >> 1; if (c < OZ) { zo[nzc] = o; zc[nzc] = c; nzc++; } }
        int ny = y + 1 - o;
        if (ny >= 0 && !(ny & 1)) { int c = ny >> 1; if (c < OY) { yo[nyc] = o; yc[nyc] = c; nyc++; } }
        int nx = x + 1 - o;
        if (nx >= 0 && !(nx & 1)) { int c = nx >> 1; if (c < OX) { xo[nxc] = o; xc[nxc] = c; nxc++; } }
    }
    int cnt = 0;
    for (int iz = 0; iz < nzc; iz++)
        for (int iy = 0; iy < nyc; iy++)
            for (int ix = 0; ix < nxc; ix++) {
                ol[cnt] = (zo[iz]*3 + yo[iy])*3 + xo[ix];
                vl[cnt] = ((b*OZ + zc[iz])*OY + yc[iy])*OX + xc[ix];
                cnt++;
            }
    return cnt;
}

/* ------------------ phase 0: zero scratch counters ------------------ */
#define TOTZ (65536 + 27 + 2*NUM_OUT)
__global__ void init_zero() {
    int i = blockIdx.x * blockDim.x + threadIdx.x;
    if (i < 65536)                      g_hist[i] = 0;
    else if (i < 65536 + 27)            g_offcnt[i - 65536] = 0;
    else if (i < 65536 + 27 + NUM_OUT)  g_keep[i - 65536 - 27] = 0;
    else if (i < TOTZ)                  g_voxcnt[i - 65536 - 27 - NUM_OUT] = 0;
}

/* ------------------ phase 1: exact rank-k select (2-pass radix-16) ------------------ */
__global__ void hist_top16(const float* __restrict__ mask, int n) {
    int i = blockIdx.x * blockDim.x + threadIdx.x;
    if (i < n) {
        unsigned u = fkey(mask[i]);
        atomicAdd(&g_hist[u >> 16], 1);
    }
}
__global__ void hist_low16(const float* __restrict__ mask, int n) {
    int i = blockIdx.x * blockDim.x + threadIdx.x;
    if (i < n) {
        unsigned u = fkey(mask[i]);
        if ((int)(u >> 16) == g_sel[0]) atomicAdd(&g_hist[u & 0xFFFFu], 1);
    }
}
__global__ void select_pass(int pass, int k) {
    __shared__ int s[256];
    int t = threadIdx.x;
    int sum = 0;
    for (int j = 0; j < 256; j++) sum += g_hist[t*256 + j];
    s[t] = sum;
    __syncthreads();
    for (int off = 1; off < 256; off <<= 1) {
        int v = (t >= off) ? s[t - off] : 0;
        __syncthreads();
        s[t] += v;
        __syncthreads();
    }
    int rank = (pass == 0) ? k : g_sel[1];
    int incl = s[t];
    int excl = incl - sum;
    if (rank >= excl && rank < incl) {
        int cum = excl;
        int bin = t * 256;
        for (int j = 0; j < 256; j++) {
            int h = g_hist[t*256 + j];
            if (rank < cum + h) { bin = t*256 + j; break; }
            cum += h;
        }
        if (pass == 0) { g_sel[0] = bin; g_sel[1] = rank - cum; }
        else           { g_thr = ((unsigned)g_sel[0] << 16) | (unsigned)bin; }
    }
    __syncthreads();
    for (int j = 0; j < 256; j++) g_hist[t*256 + j] = 0;
}

/* ------------------ phase 2: rulebook (per-offset AND per-voxel counts) ------------ */
__global__ void count_pairs(const int* __restrict__ coors, int n) {
    __shared__ int s[27];
    if (threadIdx.x < 27) s[threadIdx.x] = 0;
    __syncthreads();
    int i = blockIdx.x * blockDim.x + threadIdx.x;
    if (i < n) {
        int4 c = ((const int4*)coors)[i];
        int ol[8], vl[8];
        int cnt = enum_off(c.x, c.y, c.z, c.w, ol, vl);
        for (int e = 0; e < cnt; e++) {
            atomicAdd(&s[ol[e]], 1);
            atomicAdd(&g_voxcnt[vl[e]], 1);
        }
    }
    __syncthreads();
    if (threadIdx.x < 27 && s[threadIdx.x]) atomicAdd(&g_offcnt[threadIdx.x], s[threadIdx.x]);
}

__global__ void prefix27() {
    if (threadIdx.x == 0) {
        int a = 0;
        for (int o = 0; o < 27; o++) {
            g_offstart[o] = a; g_cursor[o] = a; a += g_offcnt[o];
        }
        g_offstart[27] = a;
    }
}

/* ---- 3-kernel exclusive scan over g_voxcnt (NUM_OUT = 625*256 exactly) ---- */
__global__ void vscan1() {            /* per-block scan, 256 elems/block */
    __shared__ int s[256];
    int t = threadIdx.x;
    int i = blockIdx.x * 256 + t;
    int v = g_voxcnt[i];
    s[t] = v;
    __syncthreads();
    for (int off = 1; off < 256; off <<= 1) {
        int u = (t >= off) ? s[t - off] : 0;
        __syncthreads();
        s[t] += u;
        __syncthreads();
    }
    g_vstart[i] = s[t] - v;           /* local exclusive */
    if (t == 255) g_vbsum[blockIdx.x] = s[255];
}
__global__ void vscan2() {            /* single block scans the 625 block sums */
    __shared__ int s[1024];
    int t = threadIdx.x;
    int v = (t < VS_BLOCKS) ? g_vbsum[t] : 0;
    s[t] = v;
    __syncthreads();
    for (int off = 1; off < 1024; off <<= 1) {
        int u = (t >= off) ? s[t - off] : 0;
        __syncthreads();
        s[t] += u;
        __syncthreads();
    }
    if (t < VS_BLOCKS) g_vboff[t] = s[t] - v;
    if (t == VS_BLOCKS - 1) g_vstart[NUM_OUT] = s[t];
}
__global__ void vscan3() {            /* add block offsets, init cursors */
    int i = blockIdx.x * 256 + threadIdx.x;
    int v = g_vstart[i] + g_vboff[blockIdx.x];
    g_vstart[i] = v;
    g_vcursor[i] = v;
}

__global__ void fill_pairs(const int* __restrict__ coors, const float* __restrict__ mask, int n) {
    __shared__ int s[27];
    __shared__ int sbase[27];
    if (threadIdx.x < 27) s[threadIdx.x] = 0;
    __syncthreads();
    int i = blockIdx.x * blockDim.x + threadIdx.x;
    int ol[8], vl[8], rk[8];
    int cnt = 0;
    if (i < n) {
        int4 c = ((const int4*)coors)[i];
        cnt = enum_off(c.x, c.y, c.z, c.w, ol, vl);
        for (int e = 0; e < cnt; e++) rk[e] = atomicAdd(&s[ol[e]], 1);
    }
    __syncthreads();
    if (threadIdx.x < 27) {
        int c = s[threadIdx.x];
        sbase[threadIdx.x] = c ? atomicAdd(&g_cursor[threadIdx.x], c) : 0;
    }
    __syncthreads();
    if (i < n) {
        bool imp = fkey(mask[i]) >= g_thr;
        for (int e = 0; e < cnt; e++) {
            int pos = sbase[ol[e]] + rk[e];
            int dst = atomicAdd(&g_vcursor[vl[e]], 1);   /* unique scratch row */
            g_pair_idx[pos] = i;
            g_pair_dst[pos] = dst;
            if (imp) g_keep[vl[e]] = 1;
        }
    }
}

/* ------------------ phase 3: per-offset GEMM -> conflict-free scratch rows -------- */
__global__ __launch_bounds__(256, 2)
void gemm_scatter(const float* __restrict__ F, const float* __restrict__ W) {
    int o = blockIdx.x;
    int s = g_offstart[o];
    int e = g_offstart[o + 1];
    int cb = s + blockIdx.y * PPB;
    if (cb >= e) return;
    int ce = min(cb + PPB, e);

    int warp = threadIdx.x >> 5;
    int lane = threadIdx.x & 31;

    /* weight column for channels (2*lane, 2*lane+1), resident in registers */
    u64 w[32];
    const float* Wo = W + o * (CIN * COUT);
#pragma unroll
    for (int k = 0; k < 32; k++)
        w[k] = *reinterpret_cast<const u64*>(Wo + k * COUT + 2 * lane);

    __shared__ u64 sf[8][2][32];

    int p = cb + warp;
    {
        float v = 0.f;
        if (p < ce) {
            int idx = g_pair_idx[p];
            v = F[idx * CIN + lane];
        }
        sf[warp][0][lane] = dup2(v);
    }
    int buf = 0;
    for (; p < ce; p += 8) {
        int dstrow = g_pair_dst[p];
        int pn = p + 8;
        float vn = 0.f;
        if (pn < ce) {
            int idxn = g_pair_idx[pn];
            vn = F[idxn * CIN + lane];
        }
        __syncwarp();
        const u64* fb = sf[warp][buf];
        u64 a0 = 0ull, a1 = 0ull, a2 = 0ull, a3 = 0ull;
#pragma unroll
        for (int k = 0; k < 32; k += 4) {
            a0 = ffma2(fb[k],     w[k],     a0);
            a1 = ffma2(fb[k + 1], w[k + 1], a1);
            a2 = ffma2(fb[k + 2], w[k + 2], a2);
            a3 = ffma2(fb[k + 3], w[k + 3], a3);
        }
        u64 acc = fadd2(fadd2(a0, a1), fadd2(a2, a3));

        /* plain coalesced 256B store — no atomics */
        ((u64*)(g_scratch + (size_t)dstrow * 64))[lane] = acc;

        buf ^= 1;
        sf[warp][buf][lane] = dup2(vn);
    }
}

/* ------------------ phase 4: segmented gather-reduce (warp per voxel) ------------- */
__global__ __launch_bounds__(256)
void gather_reduce(float* __restrict__ out) {
    int v = (blockIdx.x * blockDim.x + threadIdx.x) >> 5;   /* warp id = voxel */
    if (v >= NUM_OUT) return;
    int lane = threadIdx.x & 31;
    int s = g_vstart[v];
    int e = g_vstart[v + 1];
    u64 a0 = 0ull, a1 = 0ull;
    int r = s;
    for (; r + 1 < e; r += 2) {
        a0 = fadd2(a0, ((const u64*)(g_scratch + (size_t)r * 64))[lane]);
        a1 = fadd2(a1, ((const u64*)(g_scratch + (size_t)(r + 1) * 64))[lane]);
    }
    if (r < e)
        a0 = fadd2(a0, ((const u64*)(g_scratch + (size_t)r * 64))[lane]);
    u64 acc = fadd2(a0, a1);
    if (!g_keep[v]) acc = 0ull;
    ((u64*)(out + (size_t)v * 64))[lane] = acc;
}

/* ------------------ launch ------------------ */
extern "C" void kernel_launch(void* const* d_in, const int* in_sizes, int n_in,
                              void* d_out, int out_size) {
    const float* F = (const float*)d_in[0];
    const int*   C = (const int*)  d_in[1];
    const float* M = (const float*)d_in[2];
    const float* W = (const float*)d_in[3];
    float* out = (float*)d_out;

    int n = in_sizes[2];
    int k = (int)((double)n * 0.5);
    int gpts = (n + 255) / 256;

    init_zero<<<(TOTZ + 255) / 256, 256>>>();

    hist_top16<<<gpts, 256>>>(M, n);
    select_pass<<<1, 256>>>(0, k);
    hist_low16<<<gpts, 256>>>(M, n);
    select_pass<<<1, 256>>>(1, 0);

    count_pairs<<<gpts, 256>>>(C, n);
    prefix27<<<1, 32>>>();
    vscan1<<<VS_BLOCKS, 256>>>();
    vscan2<<<1, 1024>>>();
    vscan3<<<VS_BLOCKS, 256>>>();
    fill_pairs<<<gpts, 256>>>(C, M, n);

    gemm_scatter<<<dim3(27, MAXCHUNK), 256>>>(F, W);

    gather_reduce<<<(NUM_OUT * 32 + 255) / 256, 256>>>(out);
}

// round 4
// speedup vs baseline: 1.2305x; 1.2305x over previous
#include <cuda_runtime.h>
#include <cstring>

typedef unsigned long long u64;

#define N_MAX   400000
#define CIN     32
#define COUT    64
#define OZ      100
#define OY      100
#define OX      8
#define NUM_OUT (2*OZ*OY*OX)           /* 160000 */
#define MAXP    (8*N_MAX)              /* 3.2M max pairs */
#define PPB     2048                   /* pairs per gemm block */
#define CHUNK   (PPB/8)                /* pairs per warp: 256 */
#define MAXCHUNK ((N_MAX + PPB - 1)/PPB)

/* ------------------ device scratch (static, no allocs) ------------------ */
__device__ int      g_hist[65536];
__device__ int      g_sel[2];
__device__ unsigned g_thr;
__device__ int      g_offcnt[27];
__device__ int      g_cursor[27];      /* 0-based cursor within each offset */
__device__ int      g_keep[NUM_OUT];
__device__ int      g_pair_idx[MAXP];
__device__ int      g_pair_vox[MAXP];

/* ------------------ helpers ------------------ */
__device__ __forceinline__ unsigned fkey(float x) {
    unsigned u = __float_as_uint(x);
    return (u & 0x80000000u) ? ~u : (u | 0x80000000u);
}
__device__ __forceinline__ u64 ffma2(u64 a, u64 b, u64 c) {
    u64 d;
    asm("fma.rn.f32x2 %0, %1, %2, %3;" : "=l"(d) : "l"(a), "l"(b), "l"(c));
    return d;
}
__device__ __forceinline__ u64 fadd2(u64 a, u64 b) {
    u64 d;
    asm("add.rn.f32x2 %0, %1, %2;" : "=l"(d) : "l"(a), "l"(b));
    return d;
}
__device__ __forceinline__ u64 dupf(float v) {
    u64 r;
    asm("mov.b64 %0, {%1, %1};" : "=l"(r) : "f"(v));
    return r;
}

/* enumerate valid (offset, output voxel) pairs for one point: <= 8 */
__device__ __forceinline__ int enum_off(int b, int z, int y, int x, int* ol, int* vl) {
    int zo[2], zc[2]; int nzc = 0;
    int yo[2], yc[2]; int nyc = 0;
    int xo[2], xc[2]; int nxc = 0;
#pragma unroll
    for (int o = 0; o < 3; o++) {
        int nz = z + 1 - o;
        if (nz >= 0 && !(nz & 1)) { int c = nz >> 1; if (c < OZ) { zo[nzc] = o; zc[nzc] = c; nzc++; } }
        int ny = y + 1 - o;
        if (ny >= 0 && !(ny & 1)) { int c = ny >> 1; if (c < OY) { yo[nyc] = o; yc[nyc] = c; nyc++; } }
        int nx = x + 1 - o;
        if (nx >= 0 && !(nx & 1)) { int c = nx >> 1; if (c < OX) { xo[nxc] = o; xc[nxc] = c; nxc++; } }
    }
    int cnt = 0;
    for (int iz = 0; iz < nzc; iz++)
        for (int iy = 0; iy < nyc; iy++)
            for (int ix = 0; ix < nxc; ix++) {
                ol[cnt] = (zo[iz]*3 + yo[iy])*3 + xo[ix];
                vl[cnt] = ((b*OZ + zc[iz])*OY + yc[iy])*OX + xc[ix];
                cnt++;
            }
    return cnt;
}

/* ------------------ kernel 1: zero scratch ------------------ */
#define TOTZ (65536 + 27 + 27 + NUM_OUT)
__global__ void init_zero() {
    int i = blockIdx.x * blockDim.x + threadIdx.x;
    if (i < 65536)                    g_hist[i] = 0;
    else if (i < 65536 + 27)          g_offcnt[i - 65536] = 0;
    else if (i < 65536 + 54)          g_cursor[i - 65536 - 27] = 0;
    else if (i < TOTZ)                g_keep[i - 65536 - 54] = 0;
}

/* ------------------ kernel 2: per-offset pair counts ------------------ */
__global__ void count_pairs(const int* __restrict__ coors, int n) {
    __shared__ int s[27];
    if (threadIdx.x < 27) s[threadIdx.x] = 0;
    __syncthreads();
    int i = blockIdx.x * blockDim.x + threadIdx.x;
    if (i < n) {
        int4 c = ((const int4*)coors)[i];
        int ol[8], vl[8];
        int cnt = enum_off(c.x, c.y, c.z, c.w, ol, vl);
        for (int e = 0; e < cnt; e++) atomicAdd(&s[ol[e]], 1);
    }
    __syncthreads();
    if (threadIdx.x < 27 && s[threadIdx.x]) atomicAdd(&g_offcnt[threadIdx.x], s[threadIdx.x]);
}

/* ------------------ kernel 3: fill compacted per-offset pair lists ---------- */
__global__ void fill_pairs(const int* __restrict__ coors, int n) {
    __shared__ int soff[27];
    __shared__ int s[27];
    __shared__ int sbase[27];
    if (threadIdx.x == 0) {             /* local exclusive scan of 27 counts */
        int a = 0;
        for (int o = 0; o < 27; o++) { soff[o] = a; a += g_offcnt[o]; }
    }
    if (threadIdx.x < 27) s[threadIdx.x] = 0;
    __syncthreads();
    int i = blockIdx.x * blockDim.x + threadIdx.x;
    int ol[8], vl[8], rk[8];
    int cnt = 0;
    if (i < n) {
        int4 c = ((const int4*)coors)[i];
        cnt = enum_off(c.x, c.y, c.z, c.w, ol, vl);
        for (int e = 0; e < cnt; e++) rk[e] = atomicAdd(&s[ol[e]], 1);
    }
    __syncthreads();
    if (threadIdx.x < 27) {
        int c = s[threadIdx.x];
        sbase[threadIdx.x] = soff[threadIdx.x] + (c ? atomicAdd(&g_cursor[threadIdx.x], c) : 0);
    }
    __syncthreads();
    if (i < n) {
        for (int e = 0; e < cnt; e++) {
            int pos = sbase[ol[e]] + rk[e];
            g_pair_idx[pos] = i;
            g_pair_vox[pos] = vl[e];
        }
    }
}

/* ------------------ kernel 4 (PROFILED): per-offset GEMM + atomic scatter ---- */
__global__ __launch_bounds__(256)
void gemm_scatter(const float* __restrict__ F, const float* __restrict__ W,
                  float* __restrict__ out) {
    __shared__ int soff[28];
    if (threadIdx.x == 0) {
        int a = 0;
        for (int o = 0; o < 27; o++) { soff[o] = a; a += g_offcnt[o]; }
        soff[27] = a;
    }
    __syncthreads();

    int o = blockIdx.x;
    int s = soff[o];
    int e = soff[o + 1];
    int cb = s + blockIdx.y * PPB;
    if (cb >= e) return;
    int ce = min(cb + PPB, e);

    int warp = threadIdx.x >> 5;
    int lane = threadIdx.x & 31;

    int ws = cb + warp * CHUNK;
    int we = min(ws + CHUNK, ce);
    if (ws >= we) return;

    /* weight column for channels (2*lane, 2*lane+1), resident in registers */
    u64 w[32];
    const float* Wo = W + o * (CIN * COUT);
#pragma unroll
    for (int k = 0; k < 32; k++)
        w[k] = *reinterpret_cast<const u64*>(Wo + k * COUT + 2 * lane);

    /* depth-4 register pipeline over pairs: f = per-lane feature element */
    float f0 = 0.f, f1 = 0.f, f2 = 0.f, f3 = 0.f;
    int   v0 = 0,   v1 = 0,   v2 = 0,   v3 = 0;
    if (ws + 0 < we) { int x = g_pair_idx[ws + 0]; f0 = F[x * CIN + lane]; v0 = g_pair_vox[ws + 0]; }
    if (ws + 1 < we) { int x = g_pair_idx[ws + 1]; f1 = F[x * CIN + lane]; v1 = g_pair_vox[ws + 1]; }
    if (ws + 2 < we) { int x = g_pair_idx[ws + 2]; f2 = F[x * CIN + lane]; v2 = g_pair_vox[ws + 2]; }
    if (ws + 3 < we) { int x = g_pair_idx[ws + 3]; f3 = F[x * CIN + lane]; v3 = g_pair_vox[ws + 3]; }

#define DO_PAIR(FV, VV, PN)                                                     \
    {                                                                           \
        float fv = (FV); int vox = (VV);                                        \
        if ((PN) < we) { int x = g_pair_idx[(PN)];                              \
                         (FV) = F[x * CIN + lane]; (VV) = g_pair_vox[(PN)]; }   \
        u64 a0 = 0ull, a1 = 0ull, a2 = 0ull, a3 = 0ull;                         \
        _Pragma("unroll")                                                       \
        for (int k = 0; k < 32; k += 4) {                                       \
            a0 = ffma2(dupf(__shfl_sync(0xFFFFFFFFu, fv, k)),     w[k],     a0);\
            a1 = ffma2(dupf(__shfl_sync(0xFFFFFFFFu, fv, k + 1)), w[k + 1], a1);\
            a2 = ffma2(dupf(__shfl_sync(0xFFFFFFFFu, fv, k + 2)), w[k + 2], a2);\
            a3 = ffma2(dupf(__shfl_sync(0xFFFFFFFFu, fv, k + 3)), w[k + 3], a3);\
        }                                                                       \
        u64 acc = fadd2(fadd2(a0, a1), fadd2(a2, a3));                          \
        u64 other = __shfl_xor_sync(0xFFFFFFFFu, acc, 1);                       \
        if ((lane & 1) == 0) {                                                  \
            float2 mine, theirs;                                                \
            memcpy(&mine, &acc, 8); memcpy(&theirs, &other, 8);                 \
            float* dst = out + (size_t)vox * COUT + (lane >> 1) * 4;            \
            asm volatile("red.global.add.v4.f32 [%0], {%1, %2, %3, %4};"        \
                         :: "l"(dst), "f"(mine.x), "f"(mine.y),                 \
                            "f"(theirs.x), "f"(theirs.y) : "memory");           \
        }                                                                       \
    }

    for (int t = ws; t < we; t += 4) {
        DO_PAIR(f0, v0, t + 4);
        if (t + 1 < we) DO_PAIR(f1, v1, t + 5);
        if (t + 2 < we) DO_PAIR(f2, v2, t + 6);
        if (t + 3 < we) DO_PAIR(f3, v3, t + 7);
    }
#undef DO_PAIR
}

/* ------------------ kernels 5-8: exact rank-k select (after GEMM) ----------- */
__global__ void hist_top16(const float* __restrict__ mask, int n) {
    int i = blockIdx.x * blockDim.x + threadIdx.x;
    if (i < n) {
        unsigned u = fkey(mask[i]);
        atomicAdd(&g_hist[u >> 16], 1);
    }
}
__global__ void hist_low16(const float* __restrict__ mask, int n) {
    int i = blockIdx.x * blockDim.x + threadIdx.x;
    if (i < n) {
        unsigned u = fkey(mask[i]);
        if ((int)(u >> 16) == g_sel[0]) atomicAdd(&g_hist[u & 0xFFFFu], 1);
    }
}
__global__ void select_pass(int pass, int k) {
    __shared__ int s[256];
    int t = threadIdx.x;
    int sum = 0;
    for (int j = 0; j < 256; j++) sum += g_hist[t*256 + j];
    s[t] = sum;
    __syncthreads();
    for (int off = 1; off < 256; off <<= 1) {
        int v = (t >= off) ? s[t - off] : 0;
        __syncthreads();
        s[t] += v;
        __syncthreads();
    }
    int rank = (pass == 0) ? k : g_sel[1];
    int incl = s[t];
    int excl = incl - sum;
    if (rank >= excl && rank < incl) {
        int cum = excl;
        int bin = t * 256;
        for (int j = 0; j < 256; j++) {
            int h = g_hist[t*256 + j];
            if (rank < cum + h) { bin = t*256 + j; break; }
            cum += h;
        }
        if (pass == 0) { g_sel[0] = bin; g_sel[1] = rank - cum; }
        else           { g_thr = ((unsigned)g_sel[0] << 16) | (unsigned)bin; }
    }
    __syncthreads();
    for (int j = 0; j < 256; j++) g_hist[t*256 + j] = 0;
}

/* ------------------ kernel 9: mark kept voxels ------------------ */
__global__ void mark_keep(const int* __restrict__ coors, const float* __restrict__ mask, int n) {
    int i = blockIdx.x * blockDim.x + threadIdx.x;
    if (i >= n) return;
    if (fkey(mask[i]) < g_thr) return;
    int4 c = ((const int4*)coors)[i];
    int ol[8], vl[8];
    int cnt = enum_off(c.x, c.y, c.z, c.w, ol, vl);
    for (int e = 0; e < cnt; e++) g_keep[vl[e]] = 1;
}

/* ------------------ kernel 10: zero rows without important contributors ----- */
__global__ void mask_out(float* __restrict__ out) {
    int i = blockIdx.x * blockDim.x + threadIdx.x;   /* over NUM_OUT*16 float4s */
    if (i >= NUM_OUT * 16) return;
    int v = i >> 4;
    if (!g_keep[v]) ((float4*)out)[i] = make_float4(0.f, 0.f, 0.f, 0.f);
}

/* ------------------ launch ------------------ */
extern "C" void kernel_launch(void* const* d_in, const int* in_sizes, int n_in,
                              void* d_out, int out_size) {
    const float* F = (const float*)d_in[0];   /* features [N,32] */
    const int*   C = (const int*)  d_in[1];   /* coors    [N,4]  */
    const float* M = (const float*)d_in[2];   /* mask     [N]    */
    const float* W = (const float*)d_in[3];   /* weight   [3,3,3,32,64] */
    float* out = (float*)d_out;

    int n = in_sizes[2];
    int k = (int)((double)n * 0.5);
    int gpts = (n + 255) / 256;

    cudaMemsetAsync(out, 0, (size_t)out_size * sizeof(float));

    init_zero<<<(TOTZ + 255) / 256, 256>>>();                 /* kernel 1 */
    count_pairs<<<gpts, 256>>>(C, n);                         /* kernel 2 */
    fill_pairs<<<gpts, 256>>>(C, n);                          /* kernel 3 */
    gemm_scatter<<<dim3(27, MAXCHUNK), 256>>>(F, W, out);     /* kernel 4 <- ncu */

    hist_top16<<<gpts, 256>>>(M, n);                          /* kernel 5 */
    select_pass<<<1, 256>>>(0, k);                            /* kernel 6 */
    hist_low16<<<gpts, 256>>>(M, n);                          /* kernel 7 */
    select_pass<<<1, 256>>>(1, 0);                            /* kernel 8 */
    mark_keep<<<gpts, 256>>>(C, M, n);                        /* kernel 9 */
    mask_out<<<(NUM_OUT * 16 + 255) / 256, 256>>>(out);       /* kernel 10 */
}

// round 5
// speedup vs baseline: 2.0053x; 1.6297x over previous
#include <cuda_runtime.h>
#include <cstring>

typedef unsigned long long u64;

#define N_MAX   400000
#define CIN     32
#define COUT    64
#define OZ      100
#define OY      100
#define OX      8
#define NUM_OUT (2*OZ*OY*OX)               /* 160000 */
#define MAXP    (8*N_MAX + 27*256)         /* padded pair-space bound */
#define GRP     16                         /* pairs per staging group */

/* ------------------ device scratch (static, no allocs) ------------------ */
__device__ int      g_hist[65536];
__device__ int      g_sel[2];
__device__ unsigned g_thr;
__device__ int      g_offcnt[27];
__device__ int      g_cursor[27];
__device__ int      g_keep[NUM_OUT];
__device__ int      g_pair_idx[MAXP];
__device__ int      g_pair_vox[MAXP];

/* ------------------ helpers ------------------ */
__device__ __forceinline__ unsigned fkey(float x) {
    unsigned u = __float_as_uint(x);
    return (u & 0x80000000u) ? ~u : (u | 0x80000000u);
}
__device__ __forceinline__ u64 ffma2(u64 a, u64 b, u64 c) {
    u64 d;
    asm("fma.rn.f32x2 %0, %1, %2, %3;" : "=l"(d) : "l"(a), "l"(b), "l"(c));
    return d;
}
__device__ __forceinline__ u64 fadd2(u64 a, u64 b) {
    u64 d;
    asm("add.rn.f32x2 %0, %1, %2;" : "=l"(d) : "l"(a), "l"(b));
    return d;
}
__device__ __forceinline__ u64 dupf(float v) {
    u64 r;
    asm("mov.b64 %0, {%1, %1};" : "=l"(r) : "f"(v));
    return r;
}

/* enumerate valid (offset, output voxel) pairs for one point: <= 8 */
__device__ __forceinline__ int enum_off(int b, int z, int y, int x, int* ol, int* vl) {
    int zo[2], zc[2]; int nzc = 0;
    int yo[2], yc[2]; int nyc = 0;
    int xo[2], xc[2]; int nxc = 0;
#pragma unroll
    for (int o = 0; o < 3; o++) {
        int nz = z + 1 - o;
        if (nz >= 0 && !(nz & 1)) { int c = nz >> 1; if (c < OZ) { zo[nzc] = o; zc[nzc] = c; nzc++; } }
        int ny = y + 1 - o;
        if (ny >= 0 && !(ny & 1)) { int c = ny >> 1; if (c < OY) { yo[nyc] = o; yc[nyc] = c; nyc++; } }
        int nx = x + 1 - o;
        if (nx >= 0 && !(nx & 1)) { int c = nx >> 1; if (c < OX) { xo[nxc] = o; xc[nxc] = c; nxc++; } }
    }
    int cnt = 0;
    for (int iz = 0; iz < nzc; iz++)
        for (int iy = 0; iy < nyc; iy++)
            for (int ix = 0; ix < nxc; ix++) {
                ol[cnt] = (zo[iz]*3 + yo[iy])*3 + xo[ix];
                vl[cnt] = ((b*OZ + zc[iz])*OY + yc[iy])*OX + xc[ix];
                cnt++;
            }
    return cnt;
}

/* ------------------ kernel 1: zero scratch ------------------ */
#define TOTZ (65536 + 27 + 27 + NUM_OUT)
__global__ void init_zero() {
    int i = blockIdx.x * blockDim.x + threadIdx.x;
    if (i < 65536)                    g_hist[i] = 0;
    else if (i < 65536 + 27)          g_offcnt[i - 65536] = 0;
    else if (i < 65536 + 54)          g_cursor[i - 65536 - 27] = 0;
    else if (i < TOTZ)                g_keep[i - 65536 - 54] = 0;
}

/* ------------------ kernel 2: per-offset pair counts ------------------ */
__global__ void count_pairs(const int* __restrict__ coors, int n) {
    __shared__ int s[27];
    if (threadIdx.x < 27) s[threadIdx.x] = 0;
    __syncthreads();
    int i = blockIdx.x * blockDim.x + threadIdx.x;
    if (i < n) {
        int4 c = ((const int4*)coors)[i];
        int ol[8], vl[8];
        int cnt = enum_off(c.x, c.y, c.z, c.w, ol, vl);
        for (int e = 0; e < cnt; e++) atomicAdd(&s[ol[e]], 1);
    }
    __syncthreads();
    if (threadIdx.x < 27 && s[threadIdx.x]) atomicAdd(&g_offcnt[threadIdx.x], s[threadIdx.x]);
}

/* ------------------ kernel 3: fill compacted per-offset pair lists ---------- */
/* offset regions start at 256-aligned positions in the padded pair space      */
__global__ void fill_pairs(const int* __restrict__ coors, int n) {
    __shared__ int soff[27];
    __shared__ int s[27];
    __shared__ int sbase[27];
    if (threadIdx.x == 0) {
        int a = 0;
        for (int o = 0; o < 27; o++) {
            soff[o] = a;
            a = (a + g_offcnt[o] + 255) & ~255;
        }
    }
    if (threadIdx.x < 27) s[threadIdx.x] = 0;
    __syncthreads();
    int i = blockIdx.x * blockDim.x + threadIdx.x;
    int ol[8], vl[8], rk[8];
    int cnt = 0;
    if (i < n) {
        int4 c = ((const int4*)coors)[i];
        cnt = enum_off(c.x, c.y, c.z, c.w, ol, vl);
        for (int e = 0; e < cnt; e++) rk[e] = atomicAdd(&s[ol[e]], 1);
    }
    __syncthreads();
    if (threadIdx.x < 27) {
        int c = s[threadIdx.x];
        sbase[threadIdx.x] = soff[threadIdx.x] + (c ? atomicAdd(&g_cursor[threadIdx.x], c) : 0);
    }
    __syncthreads();
    if (i < n) {
        for (int e = 0; e < cnt; e++) {
            int pos = sbase[ol[e]] + rk[e];
            g_pair_idx[pos] = i;
            g_pair_vox[pos] = vl[e];
        }
    }
}

/* ------------------ kernel 4 (PROFILED): persistent GEMM + atomic scatter ---- */
__global__ __launch_bounds__(256)
void gemm_scatter(const float* __restrict__ F, const float* __restrict__ W,
                  float* __restrict__ out) {
    __shared__ int soff[28];
    __shared__ int scnt[27];
    __shared__ u64 sf[8][GRP][32];      /* per-warp staged f32x2-dup features: 32KB */
    if (threadIdx.x == 0) {
        int a = 0;
        for (int o = 0; o < 27; o++) {
            soff[o] = a;
            int c = g_offcnt[o];
            scnt[o] = c;
            a = (a + c + 255) & ~255;
        }
        soff[27] = a;
    }
    __syncthreads();
    int total = soff[27];
    int nchunks = (total + 2047) >> 11;

    int warp = threadIdx.x >> 5;
    int lane = threadIdx.x & 31;

    for (int c = blockIdx.x; c < nchunks; c += gridDim.x) {
        int ws = (c << 11) + warp * 256;
        if (ws >= total) continue;
        /* find offset region containing ws */
        int o = 0;
#pragma unroll
        for (int j = 1; j < 27; j++) if (soff[j] <= ws) o = j;
        int realend = soff[o] + scnt[o];
        if (ws >= realend) continue;            /* warp chunk entirely padding */
        int we = min(ws + 256, realend);

        /* weight columns for channels (2*lane, 2*lane+1) */
        u64 w[32];
        const float* Wo = W + o * (CIN * COUT);
#pragma unroll
        for (int k = 0; k < 32; k++)
            w[k] = *reinterpret_cast<const u64*>(Wo + k * COUT + 2 * lane);

        for (int gb = ws; gb < we; gb += GRP) {
            int npair = min(GRP, we - gb);
            /* lanes 0..15 fetch pair descriptors */
            int p = gb + lane;
            int pidx = 0, pvox = 0;
            if (lane < GRP && p < we) { pidx = g_pair_idx[p]; pvox = g_pair_vox[p]; }
            __syncwarp();
            /* stage: one coalesced 128B row per pair, duplicated to f32x2 */
            if (npair == GRP) {
#pragma unroll
                for (int pp = 0; pp < GRP; pp++) {
                    int xi = __shfl_sync(0xFFFFFFFFu, pidx, pp);
                    sf[warp][pp][lane] = dupf(F[xi * CIN + lane]);
                }
            } else {
                for (int pp = 0; pp < npair; pp++) {
                    int xi = __shfl_sync(0xFFFFFFFFu, pidx, pp);
                    sf[warp][pp][lane] = dupf(F[xi * CIN + lane]);
                }
            }
            __syncwarp();

#define COMPUTE_PAIR(PP)                                                        \
            {                                                                   \
                int vox = __shfl_sync(0xFFFFFFFFu, pvox, (PP));                 \
                const ulonglong2* fb = (const ulonglong2*)sf[warp][(PP)];       \
                u64 a0 = 0ull, a1 = 0ull, a2 = 0ull, a3 = 0ull;                 \
                _Pragma("unroll")                                               \
                for (int kk = 0; kk < 16; kk += 2) {                            \
                    ulonglong2 qa = fb[kk];                                     \
                    ulonglong2 qb = fb[kk + 1];                                 \
                    a0 = ffma2(qa.x, w[2*kk],     a0);                          \
                    a1 = ffma2(qa.y, w[2*kk + 1], a1);                          \
                    a2 = ffma2(qb.x, w[2*kk + 2], a2);                          \
                    a3 = ffma2(qb.y, w[2*kk + 3], a3);                          \
                }                                                               \
                u64 acc = fadd2(fadd2(a0, a1), fadd2(a2, a3));                  \
                u64 other = __shfl_xor_sync(0xFFFFFFFFu, acc, 1);               \
                if ((lane & 1) == 0) {                                          \
                    float2 mine, theirs;                                        \
                    memcpy(&mine, &acc, 8); memcpy(&theirs, &other, 8);         \
                    float* dst = out + (size_t)vox * COUT + (lane >> 1) * 4;    \
                    asm volatile("red.global.add.v4.f32 [%0], {%1, %2, %3, %4};"\
                                 :: "l"(dst), "f"(mine.x), "f"(mine.y),         \
                                    "f"(theirs.x), "f"(theirs.y) : "memory");   \
                }                                                               \
            }

            if (npair == GRP) {
#pragma unroll
                for (int pp = 0; pp < GRP; pp++) COMPUTE_PAIR(pp);
            } else {
                for (int pp = 0; pp < npair; pp++) COMPUTE_PAIR(pp);
            }
#undef COMPUTE_PAIR
            __syncwarp();
        }
    }
}

/* ------------------ kernels 5-9: exact rank-k select ------------------ */
__global__ void hist_top16(const float* __restrict__ mask, int n) {
    int i = blockIdx.x * blockDim.x + threadIdx.x;
    if (i < n) {
        unsigned u = fkey(mask[i]);
        atomicAdd(&g_hist[u >> 16], 1);
    }
}
__global__ void hist_low16(const float* __restrict__ mask, int n) {
    int i = blockIdx.x * blockDim.x + threadIdx.x;
    if (i < n) {
        unsigned u = fkey(mask[i]);
        if ((int)(u >> 16) == g_sel[0]) atomicAdd(&g_hist[u & 0xFFFFu], 1);
    }
}
__global__ void clear_hist() {
    g_hist[blockIdx.x * 256 + threadIdx.x] = 0;
}
__global__ void select_pass(int pass, int k) {
    __shared__ int s[1024];
    int t = threadIdx.x;
    const int4* h4 = (const int4*)&g_hist[t * 64];
    int sum = 0;
#pragma unroll
    for (int j = 0; j < 16; j++) {
        int4 v = h4[j];
        sum += v.x + v.y + v.z + v.w;
    }
    s[t] = sum;
    __syncthreads();
    for (int off = 1; off < 1024; off <<= 1) {
        int v = (t >= off) ? s[t - off] : 0;
        __syncthreads();
        s[t] += v;
        __syncthreads();
    }
    int rank = (pass == 0) ? k : g_sel[1];
    int incl = s[t];
    int excl = incl - sum;
    if (rank >= excl && rank < incl) {
        int cum = excl;
        int bin = t * 64;
        for (int j = 0; j < 64; j++) {
            int h = g_hist[t * 64 + j];
            if (rank < cum + h) { bin = t * 64 + j; break; }
            cum += h;
        }
        if (pass == 0) { g_sel[0] = bin; g_sel[1] = rank - cum; }
        else           { g_thr = ((unsigned)g_sel[0] << 16) | (unsigned)bin; }
    }
}

/* ------------------ kernel 10: mark kept voxels ------------------ */
__global__ void mark_keep(const int* __restrict__ coors, const float* __restrict__ mask, int n) {
    int i = blockIdx.x * blockDim.x + threadIdx.x;
    if (i >= n) return;
    if (fkey(mask[i]) < g_thr) return;
    int4 c = ((const int4*)coors)[i];
    int ol[8], vl[8];
    int cnt = enum_off(c.x, c.y, c.z, c.w, ol, vl);
    for (int e = 0; e < cnt; e++) g_keep[vl[e]] = 1;
}

/* ------------------ kernel 11: zero rows without important contributors ----- */
__global__ void mask_out(float* __restrict__ out) {
    int i = blockIdx.x * blockDim.x + threadIdx.x;
    if (i >= NUM_OUT * 16) return;
    int v = i >> 4;
    if (!g_keep[v]) ((float4*)out)[i] = make_float4(0.f, 0.f, 0.f, 0.f);
}

/* ------------------ launch ------------------ */
extern "C" void kernel_launch(void* const* d_in, const int* in_sizes, int n_in,
                              void* d_out, int out_size) {
    const float* F = (const float*)d_in[0];   /* features [N,32] */
    const int*   C = (const int*)  d_in[1];   /* coors    [N,4]  */
    const float* M = (const float*)d_in[2];   /* mask     [N]    */
    const float* W = (const float*)d_in[3];   /* weight   [3,3,3,32,64] */
    float* out = (float*)d_out;

    int n = in_sizes[2];
    int k = (int)((double)n * 0.5);
    int gpts = (n + 255) / 256;

    cudaMemsetAsync(out, 0, (size_t)out_size * sizeof(float));

    init_zero<<<(TOTZ + 255) / 256, 256>>>();                 /* kernel 1 */
    count_pairs<<<gpts, 256>>>(C, n);                         /* kernel 2 */
    fill_pairs<<<gpts, 256>>>(C, n);                          /* kernel 3 */
    gemm_scatter<<<592, 256>>>(F, W, out);                    /* kernel 4 <- ncu */

    hist_top16<<<gpts, 256>>>(M, n);                          /* kernel 5 */
    select_pass<<<1, 1024>>>(0, k);                           /* kernel 6 */
    clear_hist<<<256, 256>>>();                               /* kernel 7 */
    hist_low16<<<gpts, 256>>>(M, n);                          /* kernel 8 */
    select_pass<<<1, 1024>>>(1, 0);                           /* kernel 9 */
    mark_keep<<<gpts, 256>>>(C, M, n);                        /* kernel 10 */
    mask_out<<<(NUM_OUT * 16 + 255) / 256, 256>>>(out);       /* kernel 11 */
}

// round 8
// speedup vs baseline: 2.8709x; 1.4316x over previous
#include <cuda_runtime.h>
#include <cuda_bf16.h>
#include <cstring>
#include <cstdint>

using u64 = unsigned long long;
using u32 = unsigned int;

#define CIN     32
#define COUT    64
#define OZ      100
#define OY      100
#define OX      8
#define NUM_OUT (2*OZ*OY*OX)               /* 160000 */
#define REGION  400128                     /* per-offset region, 128-aligned */

/* ------------------ device scratch (static, no allocs) ------------------ */
__device__ int      g_hist[65536];
__device__ int      g_sel[2];
__device__ unsigned g_thr;
__device__ int      g_cursor[27];
__device__ int      g_keep[NUM_OUT];
__device__ int      g_pair_idx[27 * REGION];
__device__ int      g_pair_vox[27 * REGION];

/* ------------------ generic helpers ------------------ */
__device__ __forceinline__ unsigned fkey(float x) {
    unsigned u = __float_as_uint(x);
    return (u & 0x80000000u) ? ~u : (u | 0x80000000u);
}

/* enumerate valid (offset, output voxel) pairs for one point: <= 8 */
__device__ __forceinline__ int enum_off(int b, int z, int y, int x, int* ol, int* vl) {
    int zo[2], zc[2]; int nzc = 0;
    int yo[2], yc[2]; int nyc = 0;
    int xo[2], xc[2]; int nxc = 0;
#pragma unroll
    for (int o = 0; o < 3; o++) {
        int nz = z + 1 - o;
        if (nz >= 0 && !(nz & 1)) { int c = nz >> 1; if (c < OZ) { zo[nzc] = o; zc[nzc] = c; nzc++; } }
        int ny = y + 1 - o;
        if (ny >= 0 && !(ny & 1)) { int c = ny >> 1; if (c < OY) { yo[nyc] = o; yc[nyc] = c; nyc++; } }
        int nx = x + 1 - o;
        if (nx >= 0 && !(nx & 1)) { int c = nx >> 1; if (c < OX) { xo[nxc] = o; xc[nxc] = c; nxc++; } }
    }
    int cnt = 0;
    for (int iz = 0; iz < nzc; iz++)
        for (int iy = 0; iy < nyc; iy++)
            for (int ix = 0; ix < nxc; ix++) {
                ol[cnt] = (zo[iz]*3 + yo[iy])*3 + xo[ix];
                vl[cnt] = ((b*OZ + zc[iz])*OY + yc[iy])*OX + xc[ix];
                cnt++;
            }
    return cnt;
}

/* ------------------ kernel 1: zero scratch ------------------ */
#define TOTZ (65536 + 27 + NUM_OUT)
__global__ void init_zero() {
    int i = blockIdx.x * blockDim.x + threadIdx.x;
    if (i < 65536)                 g_hist[i] = 0;
    else if (i < 65536 + 27)       g_cursor[i - 65536] = 0;
    else if (i < TOTZ)             g_keep[i - 65536 - 27] = 0;
}

/* ------------------ kernel 2: fill rulebook + mask histogram ---------------- */
__global__ void fill_hist(const int* __restrict__ coors, const float* __restrict__ mask, int n) {
    __shared__ int s[27];
    __shared__ int sbase[27];
    if (threadIdx.x < 27) s[threadIdx.x] = 0;
    __syncthreads();
    int i = blockIdx.x * blockDim.x + threadIdx.x;
    int ol[8], vl[8], rk[8];
    int cnt = 0;
    if (i < n) {
        atomicAdd(&g_hist[fkey(mask[i]) >> 16], 1);
        int4 c = ((const int4*)coors)[i];
        cnt = enum_off(c.x, c.y, c.z, c.w, ol, vl);
        for (int e = 0; e < cnt; e++) rk[e] = atomicAdd(&s[ol[e]], 1);
    }
    __syncthreads();
    if (threadIdx.x < 27) {
        int c = s[threadIdx.x];
        sbase[threadIdx.x] = c ? atomicAdd(&g_cursor[threadIdx.x], c) : 0;
    }
    __syncthreads();
    if (i < n) {
        for (int e = 0; e < cnt; e++) {
            int pos = ol[e] * REGION + sbase[ol[e]] + rk[e];
            g_pair_idx[pos] = i;
            g_pair_vox[pos] = vl[e];
        }
    }
}

/* ------------------ kernel 3/7: radix select pass ------------------ */
__global__ void select_pass(int pass, int k) {
    __shared__ int s[1024];
    int t = threadIdx.x;
    const int4* h4 = (const int4*)&g_hist[t * 64];
    int sum = 0;
#pragma unroll
    for (int j = 0; j < 16; j++) {
        int4 v = h4[j];
        sum += v.x + v.y + v.z + v.w;
    }
    s[t] = sum;
    __syncthreads();
    for (int off = 1; off < 1024; off <<= 1) {
        int v = (t >= off) ? s[t - off] : 0;
        __syncthreads();
        s[t] += v;
        __syncthreads();
    }
    int rank = (pass == 0) ? k : g_sel[1];
    int incl = s[t];
    int excl = incl - sum;
    if (rank >= excl && rank < incl) {
        int cum = excl;
        int bin = t * 64;
        for (int j = 0; j < 64; j++) {
            int h = g_hist[t * 64 + j];
            if (rank < cum + h) { bin = t * 64 + j; break; }
            cum += h;
        }
        if (pass == 0) { g_sel[0] = bin; g_sel[1] = rank - cum; }
        else           { g_thr = ((unsigned)g_sel[0] << 16) | (unsigned)bin; }
    }
}

/* ------------------ bf16 helpers ------------------ */
__device__ __forceinline__ void split2(float x, float y, u32& hi, u32& lo) {
    __nv_bfloat162 h2 = __floats2bfloat162_rn(x, y);
    float rx = x - __bfloat162float(h2.x);
    float ry = y - __bfloat162float(h2.y);
    __nv_bfloat162 l2 = __floats2bfloat162_rn(rx, ry);
    memcpy(&hi, &h2, 4);
    memcpy(&lo, &l2, 4);
}
__device__ __forceinline__ void loadA(const float* __restrict__ F, int idx, int col,
                                      u32& hi, u32& lo) {
    if (idx < 0) { hi = 0u; lo = 0u; return; }
    float2 f = *(const float2*)(F + idx * CIN + col);
    split2(f.x, f.y, hi, lo);
}
#define MMA16816(C0,C1,C2,C3, A0,A1,A2,A3, B0,B1) \
    asm volatile("mma.sync.aligned.m16n8k16.row.col.f32.bf16.bf16.f32 " \
                 "{%0,%1,%2,%3}, {%4,%5,%6,%7}, {%8,%9}, {%0,%1,%2,%3};" \
                 : "+f"(C0), "+f"(C1), "+f"(C2), "+f"(C3) \
                 : "r"(A0), "r"(A1), "r"(A2), "r"(A3), "r"(B0), "r"(B1))

/* ------------------ kernel 4 (PROFILED): persistent HMMA GEMM --------------- */
__global__ __launch_bounds__(256)
void gemm_mma(const float* __restrict__ F, const float* __restrict__ W,
              float* __restrict__ out) {
    __shared__ int sprefix[28];        /* chunk-count prefix over offsets */
    __shared__ int scnt[27];
    __shared__ u32 swhi[64][17];       /* weight hi, [n][k/2] bf16x2, padded */
    __shared__ u32 swlo[64][17];

    int tid  = threadIdx.x;
    int wid  = tid >> 5;
    int lane = tid & 31;
    int g    = lane >> 2;              /* mma group id (row) */
    int iq   = lane & 3;               /* mma in-group id (col quad) */

    if (tid == 0) {
        int a = 0;
        for (int o = 0; o < 27; o++) {
            int c = g_cursor[o];
            scnt[o] = c;
            sprefix[o] = a;
            a += (c + 127) >> 7;
        }
        sprefix[27] = a;
    }
    __syncthreads();
    int total = sprefix[27];

    int prev_o = -1;
    u32 bhi[8][2][2], blo[8][2][2];    /* [ntile][kfrag][reg] */

    for (int rc = blockIdx.x; rc < total; rc += gridDim.x) {
        int o = 0;
#pragma unroll
        for (int j = 1; j < 27; j++) if (sprefix[j] <= rc) o = j;
        int ws  = (rc - sprefix[o]) << 7;
        int cnt = scnt[o];

        if (o != prev_o) {
            __syncthreads();           /* everyone done with previous smem W */
            const float* Wo = W + o * (CIN * COUT);
            for (int e = tid; e < CIN * COUT; e += 256) {
                int k = e >> 6, n = e & 63;
                float w = Wo[e];
                __nv_bfloat16 h = __float2bfloat16(w);
                __nv_bfloat16 l = __float2bfloat16(w - __bfloat162float(h));
                ((__nv_bfloat16*)&swhi[n][k >> 1])[k & 1] = h;
                ((__nv_bfloat16*)&swlo[n][k >> 1])[k & 1] = l;
            }
            __syncthreads();
#pragma unroll
            for (int j = 0; j < 8; j++) {
                int n = 8 * j + g;
#pragma unroll
                for (int kf = 0; kf < 2; kf++)
#pragma unroll
                    for (int h = 0; h < 2; h++) {
                        int m = 8 * kf + 4 * h + iq;
                        bhi[j][kf][h] = swhi[n][m];
                        blo[j][kf][h] = swlo[n][m];
                    }
            }
            prev_o = o;
        }

        int gs = ws + wid * 16;        /* this warp's 16-pair group */
        if (gs >= cnt) continue;
        int npair = min(16, cnt - gs);
        int pbase = o * REGION + gs;

        int pidx = -1, pvox = -1;
        if (lane < npair) { pidx = g_pair_idx[pbase + lane]; pvox = g_pair_vox[pbase + lane]; }
        int ig  = __shfl_sync(0xFFFFFFFFu, pidx, g);
        int ig8 = __shfl_sync(0xFFFFFFFFu, pidx, g + 8);
        int vg  = __shfl_sync(0xFFFFFFFFu, pvox, g);
        int vg8 = __shfl_sync(0xFFFFFFFFu, pvox, g + 8);

        /* A fragments (hi/lo split) */
        u32 ahi[2][4], alo[2][4];
#pragma unroll
        for (int kf = 0; kf < 2; kf++) {
            int c0 = 16 * kf + 2 * iq;
            loadA(F, ig,  c0,     ahi[kf][0], alo[kf][0]);
            loadA(F, ig8, c0,     ahi[kf][1], alo[kf][1]);
            loadA(F, ig,  c0 + 8, ahi[kf][2], alo[kf][2]);
            loadA(F, ig8, c0 + 8, ahi[kf][3], alo[kf][3]);
        }

#pragma unroll
        for (int j = 0; j < 8; j++) {
            float c0 = 0.f, c1 = 0.f, c2 = 0.f, c3 = 0.f;
#pragma unroll
            for (int kf = 0; kf < 2; kf++) {
                MMA16816(c0,c1,c2,c3, ahi[kf][0],ahi[kf][1],ahi[kf][2],ahi[kf][3],
                         bhi[j][kf][0], bhi[j][kf][1]);
                MMA16816(c0,c1,c2,c3, ahi[kf][0],ahi[kf][1],ahi[kf][2],ahi[kf][3],
                         blo[j][kf][0], blo[j][kf][1]);
                MMA16816(c0,c1,c2,c3, alo[kf][0],alo[kf][1],alo[kf][2],alo[kf][3],
                         bhi[j][kf][0], bhi[j][kf][1]);
            }
            /* epilogue for n-tile j: pair lanes (iq, iq^1) -> float4 red */
            u64 p01 = ((u64)__float_as_uint(c1) << 32) | (u64)__float_as_uint(c0);
            u64 p23 = ((u64)__float_as_uint(c3) << 32) | (u64)__float_as_uint(c2);
            u64 q01 = __shfl_xor_sync(0xFFFFFFFFu, p01, 1);
            u64 q23 = __shfl_xor_sync(0xFFFFFFFFu, p23, 1);
            if (!(iq & 1)) {
                int col = 8 * j + 2 * iq;
                if (vg >= 0) {
                    float* dst = out + (size_t)vg * COUT + col;
                    asm volatile("red.global.add.v4.f32 [%0], {%1, %2, %3, %4};"
                                 :: "l"(dst), "f"(c0), "f"(c1),
                                    "f"(__uint_as_float((u32)q01)),
                                    "f"(__uint_as_float((u32)(q01 >> 32)))
                                 : "memory");
                }
                if (vg8 >= 0) {
                    float* dst = out + (size_t)vg8 * COUT + col;
                    asm volatile("red.global.add.v4.f32 [%0], {%1, %2, %3, %4};"
                                 :: "l"(dst), "f"(c2), "f"(c3),
                                    "f"(__uint_as_float((u32)q23)),
                                    "f"(__uint_as_float((u32)(q23 >> 32)))
                                 : "memory");
                }
            }
        }
    }
}

/* ------------------ kernel 5: clear hist for pass 2 ------------------ */
__global__ void clear_hist() {
    g_hist[blockIdx.x * 256 + threadIdx.x] = 0;
}

/* ------------------ kernel 6: low-16 histogram ------------------ */
__global__ void hist_low16(const float* __restrict__ mask, int n) {
    int i = blockIdx.x * blockDim.x + threadIdx.x;
    if (i < n) {
        unsigned u = fkey(mask[i]);
        if ((int)(u >> 16) == g_sel[0]) atomicAdd(&g_hist[u & 0xFFFFu], 1);
    }
}

/* ------------------ kernel 8: mark kept voxels ------------------ */
__global__ void mark_keep(const int* __restrict__ coors, const float* __restrict__ mask, int n) {
    int i = blockIdx.x * blockDim.x + threadIdx.x;
    if (i >= n) return;
    if (fkey(mask[i]) < g_thr) return;
    int4 c = ((const int4*)coors)[i];
    int ol[8], vl[8];
    int cnt = enum_off(c.x, c.y, c.z, c.w, ol, vl);
    for (int e = 0; e < cnt; e++) g_keep[vl[e]] = 1;
}

/* ------------------ kernel 9: zero non-kept rows ------------------ */
__global__ void mask_out(float* __restrict__ out) {
    int i = blockIdx.x * blockDim.x + threadIdx.x;
    if (i >= NUM_OUT * 16) return;
    int v = i >> 4;
    if (!g_keep[v]) ((float4*)out)[i] = make_float4(0.f, 0.f, 0.f, 0.f);
}

/* ------------------ launch ------------------ */
extern "C" void kernel_launch(void* const* d_in, const int* in_sizes, int n_in,
                              void* d_out, int out_size) {
    const float* F = (const float*)d_in[0];   /* features [N,32] */
    const int*   C = (const int*)  d_in[1];   /* coors    [N,4]  */
    const float* M = (const float*)d_in[2];   /* mask     [N]    */
    const float* W = (const float*)d_in[3];   /* weight   [3,3,3,32,64] */
    float* out = (float*)d_out;

    int n = in_sizes[2];
    int k = (int)((double)n * 0.5);
    int gpts = (n + 255) / 256;

    cudaMemsetAsync(out, 0, (size_t)out_size * sizeof(float));

    init_zero<<<(TOTZ + 255) / 256, 256>>>();                 /* kernel 1 */
    fill_hist<<<gpts, 256>>>(C, M, n);                        /* kernel 2 */
    select_pass<<<1, 1024>>>(0, k);                           /* kernel 3 */
    gemm_mma<<<296, 256>>>(F, W, out);                        /* kernel 4 <- ncu */

    clear_hist<<<256, 256>>>();                               /* kernel 5 */
    hist_low16<<<gpts, 256>>>(M, n);                          /* kernel 6 */
    select_pass<<<1, 1024>>>(1, 0);                           /* kernel 7 */
    mark_keep<<<gpts, 256>>>(C, M, n);                        /* kernel 8 */
    mask_out<<<(NUM_OUT * 16 + 255) / 256, 256>>>(out);       /* kernel 9 */
}

// round 9
// speedup vs baseline: 3.2439x; 1.1299x over previous
#include <cuda_runtime.h>
#include <cuda_bf16.h>
#include <cstring>
#include <cstdint>

using u64 = unsigned long long;
using u32 = unsigned int;

#define CIN     32
#define COUT    64
#define OZ      100
#define OY      100
#define OX      8
#define NUM_OUT (2*OZ*OY*OX)               /* 160000 */
#define REGION  400128                     /* per-offset region, 256-aligned */
#define GRID_GEMM 444

/* ------------------ device scratch (static, no allocs) ------------------ */
__device__ int      g_hist[65536];         /* zero-init; selects self-clear */
__device__ int      g_sel[2];
__device__ unsigned g_thr;
__device__ int      g_cursor[27];
__device__ int      g_keep[NUM_OUT];
__device__ int      g_pair_idx[27 * REGION];
__device__ int      g_pair_vox[27 * REGION];

/* ------------------ generic helpers ------------------ */
__device__ __forceinline__ unsigned fkey(float x) {
    unsigned u = __float_as_uint(x);
    return (u & 0x80000000u) ? ~u : (u | 0x80000000u);
}

/* enumerate valid (offset, output voxel) pairs for one point: <= 8 */
__device__ __forceinline__ int enum_off(int b, int z, int y, int x, int* ol, int* vl) {
    int zo[2], zc[2]; int nzc = 0;
    int yo[2], yc[2]; int nyc = 0;
    int xo[2], xc[2]; int nxc = 0;
#pragma unroll
    for (int o = 0; o < 3; o++) {
        int nz = z + 1 - o;
        if (nz >= 0 && !(nz & 1)) { int c = nz >> 1; if (c < OZ) { zo[nzc] = o; zc[nzc] = c; nzc++; } }
        int ny = y + 1 - o;
        if (ny >= 0 && !(ny & 1)) { int c = ny >> 1; if (c < OY) { yo[nyc] = o; yc[nyc] = c; nyc++; } }
        int nx = x + 1 - o;
        if (nx >= 0 && !(nx & 1)) { int c = nx >> 1; if (c < OX) { xo[nxc] = o; xc[nxc] = c; nxc++; } }
    }
    int cnt = 0;
    for (int iz = 0; iz < nzc; iz++)
        for (int iy = 0; iy < nyc; iy++)
            for (int ix = 0; ix < nxc; ix++) {
                ol[cnt] = (zo[iz]*3 + yo[iy])*3 + xo[ix];
                vl[cnt] = ((b*OZ + zc[iz])*OY + yc[iy])*OX + xc[ix];
                cnt++;
            }
    return cnt;
}

/* ------------------ kernel 1: zero scratch (hist not needed: self-clearing) */
#define TOTZ (27 + NUM_OUT)
__global__ void init_zero() {
    int i = blockIdx.x * blockDim.x + threadIdx.x;
    if (i < 27)        g_cursor[i] = 0;
    else if (i < TOTZ) g_keep[i - 27] = 0;
}

/* ------------------ kernel 2: fill rulebook + mask histogram ---------------- */
__global__ void fill_hist(const int* __restrict__ coors, const float* __restrict__ mask, int n) {
    __shared__ int s[27];
    __shared__ int sbase[27];
    if (threadIdx.x < 27) s[threadIdx.x] = 0;
    __syncthreads();
    int i = blockIdx.x * blockDim.x + threadIdx.x;
    int ol[8], vl[8], rk[8];
    int cnt = 0;
    if (i < n) {
        atomicAdd(&g_hist[fkey(mask[i]) >> 16], 1);
        int4 c = ((const int4*)coors)[i];
        cnt = enum_off(c.x, c.y, c.z, c.w, ol, vl);
        for (int e = 0; e < cnt; e++) rk[e] = atomicAdd(&s[ol[e]], 1);
    }
    __syncthreads();
    if (threadIdx.x < 27) {
        int c = s[threadIdx.x];
        sbase[threadIdx.x] = c ? atomicAdd(&g_cursor[threadIdx.x], c) : 0;
    }
    __syncthreads();
    if (i < n) {
        for (int e = 0; e < cnt; e++) {
            int pos = ol[e] * REGION + sbase[ol[e]] + rk[e];
            g_pair_idx[pos] = i;
            g_pair_vox[pos] = vl[e];
        }
    }
}

/* ------------------ kernel 3/7: radix select pass (self-clearing) ----------- */
__global__ void select_pass(int pass, int k) {
    __shared__ int s[1024];
    int t = threadIdx.x;
    const int4* h4 = (const int4*)&g_hist[t * 64];
    int sum = 0;
#pragma unroll
    for (int j = 0; j < 16; j++) {
        int4 v = h4[j];
        sum += v.x + v.y + v.z + v.w;
    }
    s[t] = sum;
    __syncthreads();
    for (int off = 1; off < 1024; off <<= 1) {
        int v = (t >= off) ? s[t - off] : 0;
        __syncthreads();
        s[t] += v;
        __syncthreads();
    }
    int rank = (pass == 0) ? k : g_sel[1];
    int incl = s[t];
    int excl = incl - sum;
    if (rank >= excl && rank < incl) {
        int cum = excl;
        int bin = t * 64;
        for (int j = 0; j < 64; j++) {
            int h = g_hist[t * 64 + j];
            if (rank < cum + h) { bin = t * 64 + j; break; }
            cum += h;
        }
        if (pass == 0) { g_sel[0] = bin; g_sel[1] = rank - cum; }
        else           { g_thr = ((unsigned)g_sel[0] << 16) | (unsigned)bin; }
    }
    /* self-clear own bins (each thread touches only its own 64 bins) */
    int4* w4 = (int4*)&g_hist[t * 64];
#pragma unroll
    for (int j = 0; j < 16; j++) w4[j] = make_int4(0, 0, 0, 0);
}

/* ------------------ bf16 helpers ------------------ */
__device__ __forceinline__ void split2(float x, float y, u32& hi, u32& lo) {
    __nv_bfloat162 h2 = __floats2bfloat162_rn(x, y);
    float rx = x - __bfloat162float(h2.x);
    float ry = y - __bfloat162float(h2.y);
    __nv_bfloat162 l2 = __floats2bfloat162_rn(rx, ry);
    memcpy(&hi, &h2, 4);
    memcpy(&lo, &l2, 4);
}
__device__ __forceinline__ void loadA(const float* __restrict__ F, int idx, int col,
                                      u32& hi, u32& lo) {
    if (idx < 0) { hi = 0u; lo = 0u; return; }
    float2 f = *(const float2*)(F + idx * CIN + col);
    split2(f.x, f.y, hi, lo);
}
#define MMA16816(C0,C1,C2,C3, A0,A1,A2,A3, B0,B1) \
    asm volatile("mma.sync.aligned.m16n8k16.row.col.f32.bf16.bf16.f32 " \
                 "{%0,%1,%2,%3}, {%4,%5,%6,%7}, {%8,%9}, {%0,%1,%2,%3};" \
                 : "+f"(C0), "+f"(C1), "+f"(C2), "+f"(C3) \
                 : "r"(A0), "r"(A1), "r"(A2), "r"(A3), "r"(B0), "r"(B1))

#define EMIT_TILE(C0,C1,C2,C3, VA, VB, J)                                       \
    {                                                                           \
        u64 p01 = ((u64)__float_as_uint(C1) << 32) | (u64)__float_as_uint(C0);  \
        u64 p23 = ((u64)__float_as_uint(C3) << 32) | (u64)__float_as_uint(C2);  \
        u64 q01 = __shfl_xor_sync(0xFFFFFFFFu, p01, 1);                         \
        u64 q23 = __shfl_xor_sync(0xFFFFFFFFu, p23, 1);                         \
        if (!(iq & 1)) {                                                        \
            int col = 8 * (J) + 2 * iq;                                         \
            if ((VA) >= 0) {                                                    \
                float* dst = out + (size_t)(VA) * COUT + col;                   \
                asm volatile("red.global.add.v4.f32 [%0], {%1, %2, %3, %4};"    \
                             :: "l"(dst), "f"(C0), "f"(C1),                     \
                                "f"(__uint_as_float((u32)q01)),                 \
                                "f"(__uint_as_float((u32)(q01 >> 32)))          \
                             : "memory");                                       \
            }                                                                   \
            if ((VB) >= 0) {                                                    \
                float* dst = out + (size_t)(VB) * COUT + col;                   \
                asm volatile("red.global.add.v4.f32 [%0], {%1, %2, %3, %4};"    \
                             :: "l"(dst), "f"(C2), "f"(C3),                     \
                                "f"(__uint_as_float((u32)q23)),                 \
                                "f"(__uint_as_float((u32)(q23 >> 32)))          \
                             : "memory");                                       \
            }                                                                   \
        }                                                                       \
    }

/* ------------------ kernel 4 (PROFILED): persistent HMMA GEMM --------------- */
__global__ __launch_bounds__(256, 3)
void gemm_mma(const float* __restrict__ F, const float* __restrict__ W,
              float* __restrict__ out) {
    __shared__ int sprefix[28];        /* 256-pair chunk prefix over offsets */
    __shared__ int scnt[27];
    __shared__ u64 sbhi[8][2][32];     /* B fragments hi: [ntile][kfrag][lane] */
    __shared__ u64 sblo[8][2][32];

    int tid  = threadIdx.x;
    int wid  = tid >> 5;
    int lane = tid & 31;
    int g    = lane >> 2;
    int iq   = lane & 3;

    if (tid == 0) {
        int a = 0;
        for (int o = 0; o < 27; o++) {
            int c = g_cursor[o];
            scnt[o] = c;
            sprefix[o] = a;
            a += (c + 255) >> 8;
        }
        sprefix[27] = a;
    }
    __syncthreads();
    int total = sprefix[27];

    /* contiguous chunk range per block: few offset changes per block */
    int per = (total + gridDim.x - 1) / gridDim.x;
    int rc0 = blockIdx.x * per;
    int rc1 = min(rc0 + per, total);

    int prev_o = -1;

    for (int rc = rc0; rc < rc1; rc++) {
        int o = 0;
#pragma unroll
        for (int j = 1; j < 27; j++) if (sprefix[j] <= rc) o = j;
        int ws  = (rc - sprefix[o]) << 8;
        int cnt = scnt[o];

        if (o != prev_o) {             /* block-uniform branch */
            __syncthreads();
            const float* Wo = W + o * (CIN * COUT);
            for (int e = tid; e < 512; e += 256) {
                int j  = e >> 6;
                int kf = (e >> 5) & 1;
                int l  = e & 31;
                int gg = l >> 2, qq = l & 3;
                int nn = 8 * j + gg;
                int m0 = 8 * kf + qq;
                int m1 = m0 + 4;
                float w00 = Wo[(2*m0    ) * COUT + nn];
                float w01 = Wo[(2*m0 + 1) * COUT + nn];
                float w10 = Wo[(2*m1    ) * COUT + nn];
                float w11 = Wo[(2*m1 + 1) * COUT + nn];
                u32 h0, l0, h1, l1;
                split2(w00, w01, h0, l0);
                split2(w10, w11, h1, l1);
                sbhi[j][kf][l] = ((u64)h1 << 32) | h0;
                sblo[j][kf][l] = ((u64)l1 << 32) | l0;
            }
            __syncthreads();
            prev_o = o;
        }

        int gs = ws + wid * 32;        /* this warp's 32-pair group */
        if (gs >= cnt) continue;
        int navail = cnt - gs;
        int pbase = o * REGION + gs;

        int pidx = -1, pvox = -1;
        if (lane < navail) { pidx = g_pair_idx[pbase + lane]; pvox = g_pair_vox[pbase + lane]; }
        int i0  = __shfl_sync(0xFFFFFFFFu, pidx, g);
        int i8  = __shfl_sync(0xFFFFFFFFu, pidx, g + 8);
        int i16 = __shfl_sync(0xFFFFFFFFu, pidx, g + 16);
        int i24 = __shfl_sync(0xFFFFFFFFu, pidx, g + 24);
        int v0  = __shfl_sync(0xFFFFFFFFu, pvox, g);
        int v8  = __shfl_sync(0xFFFFFFFFu, pvox, g + 8);
        int v16 = __shfl_sync(0xFFFFFFFFu, pvox, g + 16);
        int v24 = __shfl_sync(0xFFFFFFFFu, pvox, g + 24);

        /* A fragments, two m16 tiles (pairs 0-15, 16-31) */
        u32 ah0[2][4], al0[2][4], ah1[2][4], al1[2][4];
#pragma unroll
        for (int kf = 0; kf < 2; kf++) {
            int c0 = 16 * kf + 2 * iq;
            loadA(F, i0,  c0,     ah0[kf][0], al0[kf][0]);
            loadA(F, i8,  c0,     ah0[kf][1], al0[kf][1]);
            loadA(F, i0,  c0 + 8, ah0[kf][2], al0[kf][2]);
            loadA(F, i8,  c0 + 8, ah0[kf][3], al0[kf][3]);
            loadA(F, i16, c0,     ah1[kf][0], al1[kf][0]);
            loadA(F, i24, c0,     ah1[kf][1], al1[kf][1]);
            loadA(F, i16, c0 + 8, ah1[kf][2], al1[kf][2]);
            loadA(F, i24, c0 + 8, ah1[kf][3], al1[kf][3]);
        }

#pragma unroll
        for (int j = 0; j < 8; j++) {
            float c00 = 0.f, c01 = 0.f, c02 = 0.f, c03 = 0.f;
            float c10 = 0.f, c11 = 0.f, c12 = 0.f, c13 = 0.f;
#pragma unroll
            for (int kf = 0; kf < 2; kf++) {
                u64 vh = sbhi[j][kf][lane];
                u64 vl = sblo[j][kf][lane];
                u32 bh0 = (u32)vh, bh1 = (u32)(vh >> 32);
                u32 bl0 = (u32)vl, bl1 = (u32)(vl >> 32);
                MMA16816(c00,c01,c02,c03, ah0[kf][0],ah0[kf][1],ah0[kf][2],ah0[kf][3], bh0, bh1);
                MMA16816(c00,c01,c02,c03, ah0[kf][0],ah0[kf][1],ah0[kf][2],ah0[kf][3], bl0, bl1);
                MMA16816(c00,c01,c02,c03, al0[kf][0],al0[kf][1],al0[kf][2],al0[kf][3], bh0, bh1);
                MMA16816(c10,c11,c12,c13, ah1[kf][0],ah1[kf][1],ah1[kf][2],ah1[kf][3], bh0, bh1);
                MMA16816(c10,c11,c12,c13, ah1[kf][0],ah1[kf][1],ah1[kf][2],ah1[kf][3], bl0, bl1);
                MMA16816(c10,c11,c12,c13, al1[kf][0],al1[kf][1],al1[kf][2],al1[kf][3], bh0, bh1);
            }
            EMIT_TILE(c00,c01,c02,c03, v0,  v8,  j);
            EMIT_TILE(c10,c11,c12,c13, v16, v24, j);
        }
    }
}

/* ------------------ kernel 6: low-16 histogram ------------------ */
__global__ void hist_low16(const float* __restrict__ mask, int n) {
    int i = blockIdx.x * blockDim.x + threadIdx.x;
    if (i < n) {
        unsigned u = fkey(mask[i]);
        if ((int)(u >> 16) == g_sel[0]) atomicAdd(&g_hist[u & 0xFFFFu], 1);
    }
}

/* ------------------ kernel 8: mark kept voxels ------------------ */
__global__ void mark_keep(const int* __restrict__ coors, const float* __restrict__ mask, int n) {
    int i = blockIdx.x * blockDim.x + threadIdx.x;
    if (i >= n) return;
    if (fkey(mask[i]) < g_thr) return;
    int4 c = ((const int4*)coors)[i];
    int ol[8], vl[8];
    int cnt = enum_off(c.x, c.y, c.z, c.w, ol, vl);
    for (int e = 0; e < cnt; e++) g_keep[vl[e]] = 1;
}

/* ------------------ kernel 9: zero non-kept rows (thread per voxel) --------- */
__global__ void mask_out(float* __restrict__ out) {
    int v = blockIdx.x * blockDim.x + threadIdx.x;
    if (v >= NUM_OUT) return;
    if (!g_keep[v]) {
        float4 z = make_float4(0.f, 0.f, 0.f, 0.f);
        float4* d = (float4*)(out + (size_t)v * COUT);
#pragma unroll
        for (int j = 0; j < 16; j++) d[j] = z;
    }
}

/* ------------------ launch ------------------ */
extern "C" void kernel_launch(void* const* d_in, const int* in_sizes, int n_in,
                              void* d_out, int out_size) {
    const float* F = (const float*)d_in[0];   /* features [N,32] */
    const int*   C = (const int*)  d_in[1];   /* coors    [N,4]  */
    const float* M = (const float*)d_in[2];   /* mask     [N]    */
    const float* W = (const float*)d_in[3];   /* weight   [3,3,3,32,64] */
    float* out = (float*)d_out;

    int n = in_sizes[2];
    int k = (int)((double)n * 0.5);
    int gpts = (n + 255) / 256;

    cudaMemsetAsync(out, 0, (size_t)out_size * sizeof(float));

    init_zero<<<(TOTZ + 255) / 256, 256>>>();                 /* kernel 1 */
    fill_hist<<<gpts, 256>>>(C, M, n);                        /* kernel 2 */
    select_pass<<<1, 1024>>>(0, k);                           /* kernel 3 */
    gemm_mma<<<GRID_GEMM, 256>>>(F, W, out);                  /* kernel 4 <- ncu */

    hist_low16<<<gpts, 256>>>(M, n);                          /* kernel 5 */
    select_pass<<<1, 1024>>>(1, 0);                           /* kernel 6 */
    mark_keep<<<gpts, 256>>>(C, M, n);                        /* kernel 7 */
    mask_out<<<(NUM_OUT + 255) / 256, 256>>>(out);            /* kernel 8 */
}

// round 10
// speedup vs baseline: 4.2623x; 1.3139x over previous
#include <cuda_runtime.h>
#include <cuda_bf16.h>
#include <cstring>
#include <cstdint>

using u64 = unsigned long long;
using u32 = unsigned int;

#define CIN     32
#define COUT    64
#define OZ      100
#define OY      100
#define OX      8
#define NUM_OUT (2*OZ*OY*OX)               /* 160000 */
#define REGION  400128                     /* per-offset region, 256-aligned */
#define GRID_GEMM 444

/* ------------------ device scratch (static, no allocs) ------------------ */
__device__ int      g_hist[65536];         /* zero-init; selects self-clear */
__device__ int      g_sel[2];
__device__ unsigned g_thr;
__device__ int      g_cursor[27];
__device__ int      g_keep[NUM_OUT];
__device__ int      g_pair_idx[27 * REGION];
__device__ int      g_pair_vox[27 * REGION];

/* ------------------ generic helpers ------------------ */
__device__ __forceinline__ unsigned fkey(float x) {
    unsigned u = __float_as_uint(x);
    return (u & 0x80000000u) ? ~u : (u | 0x80000000u);
}

/* enumerate valid (offset, output voxel) pairs for one point: <= 8 */
__device__ __forceinline__ int enum_off(int b, int z, int y, int x, int* ol, int* vl) {
    int zo[2], zc[2]; int nzc = 0;
    int yo[2], yc[2]; int nyc = 0;
    int xo[2], xc[2]; int nxc = 0;
#pragma unroll
    for (int o = 0; o < 3; o++) {
        int nz = z + 1 - o;
        if (nz >= 0 && !(nz & 1)) { int c = nz >> 1; if (c < OZ) { zo[nzc] = o; zc[nzc] = c; nzc++; } }
        int ny = y + 1 - o;
        if (ny >= 0 && !(ny & 1)) { int c = ny >> 1; if (c < OY) { yo[nyc] = o; yc[nyc] = c; nyc++; } }
        int nx = x + 1 - o;
        if (nx >= 0 && !(nx & 1)) { int c = nx >> 1; if (c < OX) { xo[nxc] = o; xc[nxc] = c; nxc++; } }
    }
    int cnt = 0;
    for (int iz = 0; iz < nzc; iz++)
        for (int iy = 0; iy < nyc; iy++)
            for (int ix = 0; ix < nxc; ix++) {
                ol[cnt] = (zo[iz]*3 + yo[iy])*3 + xo[ix];
                vl[cnt] = ((b*OZ + zc[iz])*OY + yc[iy])*OX + xc[ix];
                cnt++;
            }
    return cnt;
}

/* ------------------ kernel 1: zero scratch (hist self-clearing) ------------- */
#define TOTZ (27 + NUM_OUT)
__global__ void init_zero() {
    int i = blockIdx.x * blockDim.x + threadIdx.x;
    if (i < 27)        g_cursor[i] = 0;
    else if (i < TOTZ) g_keep[i - 27] = 0;
}

/* ------------------ kernel 2: fill rulebook + mask histogram ---------------- */
__global__ void fill_hist(const int* __restrict__ coors, const float* __restrict__ mask, int n) {
    __shared__ int s[27];
    __shared__ int sbase[27];
    if (threadIdx.x < 27) s[threadIdx.x] = 0;
    __syncthreads();
    int i = blockIdx.x * blockDim.x + threadIdx.x;
    int ol[8], vl[8], rk[8];
    int cnt = 0;
    if (i < n) {
        atomicAdd(&g_hist[fkey(mask[i]) >> 16], 1);
        int4 c = ((const int4*)coors)[i];
        cnt = enum_off(c.x, c.y, c.z, c.w, ol, vl);
        for (int e = 0; e < cnt; e++) rk[e] = atomicAdd(&s[ol[e]], 1);
    }
    __syncthreads();
    if (threadIdx.x < 27) {
        int c = s[threadIdx.x];
        sbase[threadIdx.x] = c ? atomicAdd(&g_cursor[threadIdx.x], c) : 0;
    }
    __syncthreads();
    if (i < n) {
        for (int e = 0; e < cnt; e++) {
            int pos = ol[e] * REGION + sbase[ol[e]] + rk[e];
            g_pair_idx[pos] = i;
            g_pair_vox[pos] = vl[e];
        }
    }
}

/* ------------------ radix select pass (self-clearing) ------------------ */
__global__ void select_pass(int pass, int k) {
    __shared__ int s[1024];
    int t = threadIdx.x;
    const int4* h4 = (const int4*)&g_hist[t * 64];
    int sum = 0;
#pragma unroll
    for (int j = 0; j < 16; j++) {
        int4 v = h4[j];
        sum += v.x + v.y + v.z + v.w;
    }
    s[t] = sum;
    __syncthreads();
    for (int off = 1; off < 1024; off <<= 1) {
        int v = (t >= off) ? s[t - off] : 0;
        __syncthreads();
        s[t] += v;
        __syncthreads();
    }
    int rank = (pass == 0) ? k : g_sel[1];
    int incl = s[t];
    int excl = incl - sum;
    if (rank >= excl && rank < incl) {
        int cum = excl;
        int bin = t * 64;
        for (int j = 0; j < 64; j++) {
            int h = g_hist[t * 64 + j];
            if (rank < cum + h) { bin = t * 64 + j; break; }
            cum += h;
        }
        if (pass == 0) { g_sel[0] = bin; g_sel[1] = rank - cum; }
        else           { g_thr = ((unsigned)g_sel[0] << 16) | (unsigned)bin; }
    }
    /* self-clear own bins */
    int4* w4 = (int4*)&g_hist[t * 64];
#pragma unroll
    for (int j = 0; j < 16; j++) w4[j] = make_int4(0, 0, 0, 0);
}

/* ------------------ bf16 helpers ------------------ */
__device__ __forceinline__ void split2(float x, float y, u32& hi, u32& lo) {
    __nv_bfloat162 h2 = __floats2bfloat162_rn(x, y);
    float rx = x - __bfloat162float(h2.x);
    float ry = y - __bfloat162float(h2.y);
    __nv_bfloat162 l2 = __floats2bfloat162_rn(rx, ry);
    memcpy(&hi, &h2, 4);
    memcpy(&lo, &l2, 4);
}
__device__ __forceinline__ void loadA(const float* __restrict__ F, int idx, int col,
                                      u32& hi, u32& lo) {
    if (idx < 0) { hi = 0u; lo = 0u; return; }
    float2 f = *(const float2*)(F + idx * CIN + col);
    split2(f.x, f.y, hi, lo);
}
#define MMA16816(C0,C1,C2,C3, A0,A1,A2,A3, B0,B1) \
    asm volatile("mma.sync.aligned.m16n8k16.row.col.f32.bf16.bf16.f32 " \
                 "{%0,%1,%2,%3}, {%4,%5,%6,%7}, {%8,%9}, {%0,%1,%2,%3};" \
                 : "+f"(C0), "+f"(C1), "+f"(C2), "+f"(C3) \
                 : "r"(A0), "r"(A1), "r"(A2), "r"(A3), "r"(B0), "r"(B1))

#define EMIT_TILE(C0,C1,C2,C3, VA, VB, J)                                       \
    {                                                                           \
        u64 p01 = ((u64)__float_as_uint(C1) << 32) | (u64)__float_as_uint(C0);  \
        u64 p23 = ((u64)__float_as_uint(C3) << 32) | (u64)__float_as_uint(C2);  \
        u64 q01 = __shfl_xor_sync(0xFFFFFFFFu, p01, 1);                         \
        u64 q23 = __shfl_xor_sync(0xFFFFFFFFu, p23, 1);                         \
        if (!(iq & 1)) {                                                        \
            int col = 8 * (J) + 2 * iq;                                         \
            if ((VA) >= 0) {                                                    \
                float* dst = out + (size_t)(VA) * COUT + col;                   \
                asm volatile("red.global.add.v4.f32 [%0], {%1, %2, %3, %4};"    \
                             :: "l"(dst), "f"(C0), "f"(C1),                     \
                                "f"(__uint_as_float((u32)q01)),                 \
                                "f"(__uint_as_float((u32)(q01 >> 32)))          \
                             : "memory");                                       \
            }                                                                   \
            if ((VB) >= 0) {                                                    \
                float* dst = out + (size_t)(VB) * COUT + col;                   \
                asm volatile("red.global.add.v4.f32 [%0], {%1, %2, %3, %4};"    \
                             :: "l"(dst), "f"(C2), "f"(C3),                     \
                                "f"(__uint_as_float((u32)q23)),                 \
                                "f"(__uint_as_float((u32)(q23 >> 32)))          \
                             : "memory");                                       \
            }                                                                   \
        }                                                                       \
    }

/* ------------------ persistent HMMA GEMM (unchanged from R9) ---------------- */
__global__ __launch_bounds__(256, 3)
void gemm_mma(const float* __restrict__ F, const float* __restrict__ W,
              float* __restrict__ out) {
    __shared__ int sprefix[28];
    __shared__ int scnt[27];
    __shared__ u64 sbhi[8][2][32];
    __shared__ u64 sblo[8][2][32];

    int tid  = threadIdx.x;
    int wid  = tid >> 5;
    int lane = tid & 31;
    int g    = lane >> 2;
    int iq   = lane & 3;

    if (tid == 0) {
        int a = 0;
        for (int o = 0; o < 27; o++) {
            int c = g_cursor[o];
            scnt[o] = c;
            sprefix[o] = a;
            a += (c + 255) >> 8;
        }
        sprefix[27] = a;
    }
    __syncthreads();
    int total = sprefix[27];

    int per = (total + gridDim.x - 1) / gridDim.x;
    int rc0 = blockIdx.x * per;
    int rc1 = min(rc0 + per, total);

    int prev_o = -1;

    for (int rc = rc0; rc < rc1; rc++) {
        int o = 0;
#pragma unroll
        for (int j = 1; j < 27; j++) if (sprefix[j] <= rc) o = j;
        int ws  = (rc - sprefix[o]) << 8;
        int cnt = scnt[o];

        if (o != prev_o) {
            __syncthreads();
            const float* Wo = W + o * (CIN * COUT);
            for (int e = tid; e < 512; e += 256) {
                int j  = e >> 6;
                int kf = (e >> 5) & 1;
                int l  = e & 31;
                int gg = l >> 2, qq = l & 3;
                int nn = 8 * j + gg;
                int m0 = 8 * kf + qq;
                int m1 = m0 + 4;
                float w00 = Wo[(2*m0    ) * COUT + nn];
                float w01 = Wo[(2*m0 + 1) * COUT + nn];
                float w10 = Wo[(2*m1    ) * COUT + nn];
                float w11 = Wo[(2*m1 + 1) * COUT + nn];
                u32 h0, l0, h1, l1;
                split2(w00, w01, h0, l0);
                split2(w10, w11, h1, l1);
                sbhi[j][kf][l] = ((u64)h1 << 32) | h0;
                sblo[j][kf][l] = ((u64)l1 << 32) | l0;
            }
            __syncthreads();
            prev_o = o;
        }

        int gs = ws + wid * 32;
        if (gs >= cnt) continue;
        int navail = cnt - gs;
        int pbase = o * REGION + gs;

        int pidx = -1, pvox = -1;
        if (lane < navail) { pidx = g_pair_idx[pbase + lane]; pvox = g_pair_vox[pbase + lane]; }
        int i0  = __shfl_sync(0xFFFFFFFFu, pidx, g);
        int i8  = __shfl_sync(0xFFFFFFFFu, pidx, g + 8);
        int i16 = __shfl_sync(0xFFFFFFFFu, pidx, g + 16);
        int i24 = __shfl_sync(0xFFFFFFFFu, pidx, g + 24);
        int v0  = __shfl_sync(0xFFFFFFFFu, pvox, g);
        int v8  = __shfl_sync(0xFFFFFFFFu, pvox, g + 8);
        int v16 = __shfl_sync(0xFFFFFFFFu, pvox, g + 16);
        int v24 = __shfl_sync(0xFFFFFFFFu, pvox, g + 24);

        u32 ah0[2][4], al0[2][4], ah1[2][4], al1[2][4];
#pragma unroll
        for (int kf = 0; kf < 2; kf++) {
            int c0 = 16 * kf + 2 * iq;
            loadA(F, i0,  c0,     ah0[kf][0], al0[kf][0]);
            loadA(F, i8,  c0,     ah0[kf][1], al0[kf][1]);
            loadA(F, i0,  c0 + 8, ah0[kf][2], al0[kf][2]);
            loadA(F, i8,  c0 + 8, ah0[kf][3], al0[kf][3]);
            loadA(F, i16, c0,     ah1[kf][0], al1[kf][0]);
            loadA(F, i24, c0,     ah1[kf][1], al1[kf][1]);
            loadA(F, i16, c0 + 8, ah1[kf][2], al1[kf][2]);
            loadA(F, i24, c0 + 8, ah1[kf][3], al1[kf][3]);
        }

#pragma unroll
        for (int j = 0; j < 8; j++) {
            float c00 = 0.f, c01 = 0.f, c02 = 0.f, c03 = 0.f;
            float c10 = 0.f, c11 = 0.f, c12 = 0.f, c13 = 0.f;
#pragma unroll
            for (int kf = 0; kf < 2; kf++) {
                u64 vh = sbhi[j][kf][lane];
                u64 vl = sblo[j][kf][lane];
                u32 bh0 = (u32)vh, bh1 = (u32)(vh >> 32);
                u32 bl0 = (u32)vl, bl1 = (u32)(vl >> 32);
                MMA16816(c00,c01,c02,c03, ah0[kf][0],ah0[kf][1],ah0[kf][2],ah0[kf][3], bh0, bh1);
                MMA16816(c00,c01,c02,c03, ah0[kf][0],ah0[kf][1],ah0[kf][2],ah0[kf][3], bl0, bl1);
                MMA16816(c00,c01,c02,c03, al0[kf][0],al0[kf][1],al0[kf][2],al0[kf][3], bh0, bh1);
                MMA16816(c10,c11,c12,c13, ah1[kf][0],ah1[kf][1],ah1[kf][2],ah1[kf][3], bh0, bh1);
                MMA16816(c10,c11,c12,c13, ah1[kf][0],ah1[kf][1],ah1[kf][2],ah1[kf][3], bl0, bl1);
                MMA16816(c10,c11,c12,c13, al1[kf][0],al1[kf][1],al1[kf][2],al1[kf][3], bh0, bh1);
            }
            EMIT_TILE(c00,c01,c02,c03, v0,  v8,  j);
            EMIT_TILE(c10,c11,c12,c13, v16, v24, j);
        }
    }
}

/* ------------------ low-16 histogram ------------------ */
__global__ void hist_low16(const float* __restrict__ mask, int n) {
    int i = blockIdx.x * blockDim.x + threadIdx.x;
    if (i < n) {
        unsigned u = fkey(mask[i]);
        if ((int)(u >> 16) == g_sel[0]) atomicAdd(&g_hist[u & 0xFFFFu], 1);
    }
}

/* ------------------ mark kept voxels ------------------ */
__global__ void mark_keep(const int* __restrict__ coors, const float* __restrict__ mask, int n) {
    int i = blockIdx.x * blockDim.x + threadIdx.x;
    if (i >= n) return;
    if (fkey(mask[i]) < g_thr) return;
    int4 c = ((const int4*)coors)[i];
    int ol[8], vl[8];
    int cnt = enum_off(c.x, c.y, c.z, c.w, ol, vl);
    for (int e = 0; e < cnt; e++) g_keep[vl[e]] = 1;
}

/* ------------------ zero non-kept rows ------------------ */
__global__ void mask_out(float* __restrict__ out) {
    int v = blockIdx.x * blockDim.x + threadIdx.x;
    if (v >= NUM_OUT) return;
    if (!g_keep[v]) {
        float4 z = make_float4(0.f, 0.f, 0.f, 0.f);
        float4* d = (float4*)(out + (size_t)v * COUT);
#pragma unroll
        for (int j = 0; j < 16; j++) d[j] = z;
    }
}

/* ------------------ launch: fork select-chain parallel to GEMM -------------- */
extern "C" void kernel_launch(void* const* d_in, const int* in_sizes, int n_in,
                              void* d_out, int out_size) {
    const float* F = (const float*)d_in[0];   /* features [N,32] */
    const int*   C = (const int*)  d_in[1];   /* coors    [N,4]  */
    const float* M = (const float*)d_in[2];   /* mask     [N]    */
    const float* W = (const float*)d_in[3];   /* weight   [3,3,3,32,64] */
    float* out = (float*)d_out;

    int n = in_sizes[2];
    int k = (int)((double)n * 0.5);
    int gpts = (n + 255) / 256;

    /* one-time handles (infrastructure, not work state) */
    static cudaStream_t s2 = ([]{
        cudaStream_t s; cudaStreamCreateWithFlags(&s, cudaStreamNonBlocking); return s;
    })();
    static cudaEvent_t evFork = ([]{
        cudaEvent_t e; cudaEventCreateWithFlags(&e, cudaEventDisableTiming); return e;
    })();
    static cudaEvent_t evJoin = ([]{
        cudaEvent_t e; cudaEventCreateWithFlags(&e, cudaEventDisableTiming); return e;
    })();

    /* main stream: rulebook build */
    cudaMemsetAsync(out, 0, (size_t)out_size * sizeof(float));
    init_zero<<<(TOTZ + 255) / 256, 256>>>();
    fill_hist<<<gpts, 256>>>(C, M, n);

    /* fork: threshold/keep chain on s2, concurrent with GEMM */
    cudaEventRecord(evFork, 0);
    cudaStreamWaitEvent(s2, evFork, 0);
    select_pass<<<1, 1024, 0, s2>>>(0, k);
    hist_low16<<<gpts, 256, 0, s2>>>(M, n);
    select_pass<<<1, 1024, 0, s2>>>(1, 0);
    mark_keep<<<gpts, 256, 0, s2>>>(C, M, n);
    cudaEventRecord(evJoin, s2);

    /* main stream: GEMM (ncu: 4th kernel on this stream) */
    gemm_mma<<<GRID_GEMM, 256>>>(F, W, out);

    /* join, then final mask */
    cudaStreamWaitEvent(0, evJoin, 0);
    mask_out<<<(NUM_OUT + 255) / 256, 256>>>(out);
}